// round 15
// baseline (speedup 1.0000x reference)
#include <cuda_runtime.h>
#include <cuda_fp16.h>
#include <cstdint>

#define B 8
#define T 2048
#define C 1024
#define H 64
#define QT2   128              // attn query tile (rows per block)
#define NQT2  (T / QT2)        // 16
#define KCHUNK 512
#define NCH    4

// ---------------- scratch (__device__ globals; no allocation allowed) -------
__device__ __half g_pacc[B * NQT2 * NCH * QT2 * H];    // fp16 split-K partials
__device__ float  g_pl[B * NQT2 * NCH * QT2];
__device__ __half g_wt[3 * H * C];          // W^T fp16: [192 n][1024 k]
// projected q/k/v as fp16 (q pre-scaled by log2(e)/32)
__device__ __half g_qh[B * T * H];
__device__ __half g_kh[B * T * H];
__device__ __half g_vh[B * T * H];

#define ONES_H2 0x3C003C00u

// ---------------- helpers ----------------------------------------------------
__device__ __forceinline__ uint32_t smem_u32(const void* p) {
    uint32_t a;
    asm("{ .reg .u64 t; cvta.to.shared.u64 t, %1; cvt.u32.u64 %0, t; }"
        : "=r"(a) : "l"(p));
    return a;
}
__device__ __forceinline__ void cp16(uint32_t saddr, const void* gptr) {
    asm volatile("cp.async.cg.shared.global [%0], [%1], 16;"
                 :: "r"(saddr), "l"(__cvta_generic_to_global(gptr)) : "memory");
}
#define CP_COMMIT() asm volatile("cp.async.commit_group;" ::: "memory")
#define CP_WAIT(n)  asm volatile("cp.async.wait_group %0;" :: "n"(n) : "memory")

__device__ __forceinline__ void ldx4(uint32_t* r, uint32_t addr) {
    asm volatile("ldmatrix.sync.aligned.m8n8.x4.shared.b16 {%0,%1,%2,%3}, [%4];"
                 : "=r"(r[0]), "=r"(r[1]), "=r"(r[2]), "=r"(r[3]) : "r"(addr));
}
__device__ __forceinline__ void ldx4t(uint32_t* r, uint32_t addr) {
    asm volatile("ldmatrix.sync.aligned.m8n8.x4.trans.shared.b16 {%0,%1,%2,%3}, [%4];"
                 : "=r"(r[0]), "=r"(r[1]), "=r"(r[2]), "=r"(r[3]) : "r"(addr));
}
__device__ __forceinline__ void mma_f16(float* c, const uint32_t* a,
                                        uint32_t b0, uint32_t b1) {
    asm volatile(
        "mma.sync.aligned.m16n8k16.row.col.f32.f16.f16.f32 "
        "{%0,%1,%2,%3}, {%4,%5,%6,%7}, {%8,%9}, {%0,%1,%2,%3};"
        : "+f"(c[0]), "+f"(c[1]), "+f"(c[2]), "+f"(c[3])
        : "r"(a[0]), "r"(a[1]), "r"(a[2]), "r"(a[3]), "r"(b0), "r"(b1));
}
__device__ __forceinline__ uint32_t packh(float lo, float hi) {
    uint32_t r;
    asm("cvt.rn.f16x2.f32 %0, %1, %2;" : "=r"(r) : "f"(hi), "f"(lo));
    return r;
}
__device__ __forceinline__ uint32_t h2ex2(uint32_t x) {
    uint32_t r;
    asm("ex2.approx.f16x2 %0, %1;" : "=r"(r) : "r"(x));
    return r;
}
__device__ __forceinline__ void sts8(uint32_t addr, uint32_t a, uint32_t b) {
    asm volatile("st.shared.v2.b32 [%0], {%1,%2};" :: "r"(addr), "r"(a), "r"(b) : "memory");
}

// ---------------------------------------------------------------------------
// W -> transposed fp16 via smem transpose. grid = 192, block = 128.
// ---------------------------------------------------------------------------
__global__ void __launch_bounds__(128) convw_kernel(
    const float* __restrict__ Wk, const float* __restrict__ Wq,
    const float* __restrict__ Wv)
{
    __shared__ float s[16][65];
    const int bid = blockIdx.x;
    const int o   = bid >> 6;
    const int k0  = (bid & 63) << 4;
    const int tid = threadIdx.x;
    const float* __restrict__ W = (o == 0) ? Wk : ((o == 1) ? Wq : Wv);

    #pragma unroll
    for (int i = 0; i < 2; i++) {
        int f = tid + 128 * i;
        int row = f >> 4, q4 = (f & 15) << 2;
        float4 v = *(const float4*)&W[(size_t)(k0 + row) * 64 + q4];
        s[row][q4 + 0] = v.x;
        s[row][q4 + 1] = v.y;
        s[row][q4 + 2] = v.z;
        s[row][q4 + 3] = v.w;
    }
    __syncthreads();

    #pragma unroll
    for (int i = 0; i < 2; i++) {
        int f = tid + 128 * i;
        int n = f >> 2, k = (f & 3) << 2;
        uint2 w;
        w.x = packh(s[k + 0][n], s[k + 1][n]);
        w.y = packh(s[k + 2][n], s[k + 3][n]);
        *(uint2*)&g_wt[((size_t)(o * 64 + n)) * 1024 + k0 + k] = w;
    }
}

// ---------------------------------------------------------------------------
// Projection GEMM — pure fp16 HMMA. x converted in-kernel.
// Block tile 64x192, warp tile 32x48, k chunk 32.
// 3-stage smem ring, ONE sync per chunk.
// smem per buffer (20480 B): A @0 (64*80), B @5120 (192*80); 3 buffers.
// ---------------------------------------------------------------------------
#define BUFSZ 20480
#define B_OFF 5120

__device__ __forceinline__ void ldg_a(const float* __restrict__ x, int m0,
                                      int ch, int tid, float4* r)
{
    const int k0 = ch << 5;
    #pragma unroll
    for (int i = 0; i < 2; i++) {
        int idx = tid + 256 * i;
        int row = idx >> 3, q = idx & 7;
        r[i] = *(const float4*)&x[(size_t)(m0 + row) * 1024 + k0 + q * 4];
    }
}
__device__ __forceinline__ void sts_a(uint32_t base, int tid, const float4* r)
{
    #pragma unroll
    for (int i = 0; i < 2; i++) {
        int idx = tid + 256 * i;
        int row = idx >> 3, q = idx & 7;
        sts8(base + row * 80 + q * 8,
             packh(r[i].x, r[i].y), packh(r[i].z, r[i].w));
    }
}
__device__ __forceinline__ void stage_b(uint32_t base, int ch, int tid)
{
    const int k0 = ch << 5;
    #pragma unroll
    for (int i = 0; i < 3; i++) {
        int idx = tid + 256 * i;
        int r = idx >> 2, q = idx & 3;
        cp16(base + B_OFF + r * 80 + q * 16, g_wt + (size_t)r * 1024 + k0 + q * 8);
    }
}

__global__ void __launch_bounds__(256, 2) proj_gemm_kernel(const float* __restrict__ x)
{
    extern __shared__ __align__(16) char sm[];
    const uint32_t smb = smem_u32(sm);

    const int tid  = threadIdx.x;
    const int wid  = tid >> 5;
    const int lane = tid & 31;
    const int wr   = wid >> 2;
    const int wc   = wid & 3;
    const int m0   = blockIdx.x * 64;

    float c[2][6][4];
    #pragma unroll
    for (int mt = 0; mt < 2; mt++)
        #pragma unroll
        for (int nt = 0; nt < 6; nt++)
            #pragma unroll
            for (int e = 0; e < 4; e++) c[mt][nt][e] = 0.f;

    const uint32_t aoff = (uint32_t)((wr * 32 + (lane & 15)) * 80 + (lane >> 4) * 16);
    const int bg = lane >> 3;
    const uint32_t boff = (uint32_t)((wc * 48 + (lane & 7) + (bg >> 1) * 8) * 80 + (bg & 1) * 16);

    float4 areg[2];
    ldg_a(x, m0, 0, tid, areg);
    sts_a(smb, tid, areg);
    stage_b(smb, 0, tid);
    CP_COMMIT();
    ldg_a(x, m0, 1, tid, areg);
    stage_b(smb + BUFSZ, 1, tid);
    CP_COMMIT();

    int bufc = 0;
    for (int ch = 0; ch < 32; ch++) {
        if (ch < 31) { CP_WAIT(1); } else { CP_WAIT(0); }
        __syncthreads();

        int b1 = bufc + 1; if (b1 >= 3) b1 -= 3;
        if (ch + 1 < 32)
            sts_a(smb + b1 * BUFSZ, tid, areg);

        const uint32_t base = smb + bufc * BUFSZ;
        #pragma unroll
        for (int k16 = 0; k16 < 2; k16++) {
            uint32_t ah[2][4], bw[3][4];
            #pragma unroll
            for (int mt = 0; mt < 2; mt++)
                ldx4(ah[mt], base + aoff + mt * (16 * 80) + k16 * 32);
            #pragma unroll
            for (int np = 0; np < 3; np++)
                ldx4(bw[np], base + B_OFF + boff + np * (16 * 80) + k16 * 32);
            #pragma unroll
            for (int mt = 0; mt < 2; mt++) {
                #pragma unroll
                for (int nt = 0; nt < 6; nt++) {
                    const int np = nt >> 1, sel = (nt & 1) * 2;
                    mma_f16(c[mt][nt], ah[mt], bw[np][sel], bw[np][sel + 1]);
                }
            }
        }

        if (ch + 2 < 32) {
            ldg_a(x, m0, ch + 2, tid, areg);
            int b2 = bufc + 2; if (b2 >= 3) b2 -= 3;
            stage_b(smb + b2 * BUFSZ, ch + 2, tid);
            CP_COMMIT();
        }
        if (++bufc == 3) bufc = 0;
    }

    // Epilogue: fp16 q/k/v (q scaled by log2(e)/32 so attn uses ex2 directly)
    #pragma unroll
    for (int mt = 0; mt < 2; mt++) {
        const int row = m0 + wr * 32 + mt * 16 + (lane >> 2);
        #pragma unroll
        for (int nt = 0; nt < 6; nt++) {
            const int ng  = wc * 48 + nt * 8;
            const int mat = ng >> 6;
            const int col = (ng & 63) + 2 * (lane & 3);
            __half* dh = (mat == 0) ? g_kh : ((mat == 1) ? g_qh : g_vh);
            const float s = (mat == 1) ? 0.04508422f : 1.0f;   // log2e/32
            *(uint32_t*)&dh[(size_t)row * 64 + col] =
                packh(c[mt][nt][0] * s, c[mt][nt][1] * s);
            *(uint32_t*)&dh[(size_t)(row + 8) * 64 + col] =
                packh(c[mt][nt][2] * s, c[mt][nt][3] * s);
        }
    }
}

// ---------------------------------------------------------------------------
// Tensor-core split-K causal attention — fp16 operands, fp32 accum.
// 128-query tiles, 256 threads (8 warps x 16 rows). grid = (NCH=4, 16, B),
// heavy qt first. KCHUNK=512. 3-stage KV ring, ONE sync per tile.
// Q (16KB) overlays all of buf2 (first written by stage(2) at iter 0, after
// the iter-0 sync that follows the Q-fragment register loads).
// 2 CTAs/SM (256 thr x ~128 regs), 16 warps/SM.
// ---------------------------------------------------------------------------
#define KVBUF   16384
#define ATTN_SMEM 49152

__device__ __forceinline__ void stage_kv(uint32_t base, int b, int s0, int tid)
{
    const size_t g0 = ((size_t)(b * T) + s0) * 64;
    #pragma unroll
    for (int i = 0; i < 2; i++) {
        int idx = tid + 256 * i;          // 0..511
        int row = idx >> 3, q = idx & 7;
        uint32_t dst = base + row * 128 + ((q ^ (row & 7)) << 4);
        size_t src = g0 + row * 64 + q * 8;
        cp16(dst,        g_kh + src);
        cp16(dst + 8192, g_vh + src);
    }
}

__global__ void __launch_bounds__(256, 2) attn_kernel(float* __restrict__ out)
{
    const int chunk = blockIdx.x;
    const int qt    = NQT2 - 1 - (int)blockIdx.y;   // heavy tiles first
    const int b     = blockIdx.z;
    const int nch   = (qt >> 2) + 1;

    const int kbeg = chunk * KCHUNK;
    const int klim = (qt + 1) * QT2;
    if (kbeg >= klim) return;
    const int ntiles = min(8, (klim - kbeg) >> 6);

    extern __shared__ __align__(16) char sm[];
    const uint32_t smb = smem_u32(sm);
    const int tid  = threadIdx.x;
    const int w    = tid >> 5;
    const int lane = tid & 31;

    // prologue: Q (full buf2 overlay, 128x128B) + KV0 in group0; KV1 in group1
    {
        const size_t gq = ((size_t)(b * T) + qt * QT2) * 64;
        #pragma unroll
        for (int i = 0; i < 4; i++) {
            int idx = tid + 256 * i;          // 0..1023
            int row = idx >> 3, q = idx & 7;
            uint32_t dst = smb + 2 * KVBUF + row * 128 + ((q ^ (row & 7)) << 4);
            cp16(dst, g_qh + gq + row * 64 + q * 8);
        }
    }
    stage_kv(smb, b, kbeg, tid);
    CP_COMMIT();
    if (ntiles > 1) {
        stage_kv(smb + KVBUF, b, kbeg + 64, tid);
        CP_COMMIT();
        CP_WAIT(1);
    } else {
        CP_WAIT(0);
    }
    __syncthreads();

    // Q fragments -> registers (warp w owns rows w*16..w*16+15)
    uint32_t qh[4][4];
    #pragma unroll
    for (int ks = 0; ks < 4; ks++) {
        int row = w * 16 + (lane & 15);
        int cg  = ks * 2 + (lane >> 4);
        ldx4(qh[ks], smb + 2 * KVBUF + row * 128 + ((cg ^ (row & 7)) << 4));
    }

    float o[8][4];
    #pragma unroll
    for (int nt = 0; nt < 8; nt++)
        #pragma unroll
        for (int e = 0; e < 4; e++) o[nt][e] = 0.f;
    float lsum[4] = {0.f, 0.f, 0.f, 0.f};

    const int rowl = w * 16 + (lane >> 2);    // local row 0..127

    int bufc = 0;
    for (int kt = 0; kt < ntiles; kt++) {
        if (kt + 1 < ntiles) { CP_WAIT(1); } else { CP_WAIT(0); }
        __syncthreads();

        const uint32_t base = smb + bufc * KVBUF;

        // ---- S' = Q . K^T (log2 domain) ----
        float c[8][4];
        #pragma unroll
        for (int nt = 0; nt < 8; nt++)
            #pragma unroll
            for (int e = 0; e < 4; e++) c[nt][e] = 0.f;

        #pragma unroll
        for (int nb = 0; nb < 4; nb++) {
            #pragma unroll
            for (int ks = 0; ks < 4; ks++) {
                int row = nb * 16 + (lane & 7) + ((lane >> 4) << 3);
                int cg  = ks * 2 + ((lane >> 3) & 1);
                uint32_t bh[4];
                ldx4(bh, base + row * 128 + ((cg ^ (row & 7)) << 4));
                mma_f16(c[2 * nb],     qh[ks], bh[0], bh[1]);
                mma_f16(c[2 * nb + 1], qh[ks], bh[2], bh[3]);
            }
        }

        // ---- pack, 2^s in f16x2, mask ----
        // tile key offset relative to the query tile base
        const int doff = kbeg + kt * 64 - qt * QT2;
        const bool diag = (doff > -64);
        const int trow = rowl - doff;       // mask threshold in tile-local keys
        uint32_t ph[8][2];
        #pragma unroll
        for (int nt = 0; nt < 8; nt++) {
            uint32_t p01 = h2ex2(packh(c[nt][0], c[nt][1]));
            uint32_t p23 = h2ex2(packh(c[nt][2], c[nt][3]));
            if (diag) {
                const int s0l = nt * 8 + ((lane & 3) << 1);
                uint32_t m01 = (s0l + 1 <= trow) ? 0xFFFFFFFFu
                             : ((s0l <= trow) ? 0x0000FFFFu : 0u);
                uint32_t m23 = (s0l + 1 <= trow + 8) ? 0xFFFFFFFFu
                             : ((s0l <= trow + 8) ? 0x0000FFFFu : 0u);
                p01 &= m01;
                p23 &= m23;
            }
            ph[nt][0] = p01;
            ph[nt][1] = p23;
        }

        // ---- O += P . V ;  l += P . 1 (tensor-core row sums) ----
        #pragma unroll
        for (int ks = 0; ks < 4; ks++) {
            uint32_t pa[4];
            pa[0] = ph[2 * ks][0];
            pa[1] = ph[2 * ks][1];
            pa[2] = ph[2 * ks + 1][0];
            pa[3] = ph[2 * ks + 1][1];
            mma_f16(lsum, pa, ONES_H2, ONES_H2);
            #pragma unroll
            for (int hb = 0; hb < 4; hb++) {
                int vrow = ks * 16 + (lane & 15);
                int cg   = hb * 2 + (lane >> 4);
                uint32_t vh[4];
                ldx4t(vh, base + 8192 + vrow * 128 + ((cg ^ (vrow & 7)) << 4));
                mma_f16(o[2 * hb],     pa, vh[0], vh[1]);
                mma_f16(o[2 * hb + 1], pa, vh[2], vh[3]);
            }
        }

        // ---- stage tile kt+2 into buf((kt+2)%3) (readers done pre-sync) ----
        if (kt + 2 < ntiles) {
            int bs = bufc + 2; if (bs >= 3) bs -= 3;
            stage_kv(smb + bs * KVBUF, b, kbeg + (kt + 2) * 64, tid);
            CP_COMMIT();
        }
        if (++bufc == 3) bufc = 0;
    }

    // ---- single-chunk tiles (qt<4, t<512): normalize + write out ----
    if (nch == 1) {
        const float i0 = 1.f / lsum[0];
        const float i2 = 1.f / lsum[2];
        const size_t ob = ((size_t)(b * T) + qt * QT2) * 64;
        #pragma unroll
        for (int nt = 0; nt < 8; nt++) {
            const int col = nt * 8 + ((lane & 3) << 1);
            float2 w0; w0.x = o[nt][0] * i0; w0.y = o[nt][1] * i0;
            float2 w1; w1.x = o[nt][2] * i2; w1.y = o[nt][3] * i2;
            *(float2*)&out[ob + (size_t)rowl * 64 + col]       = w0;
            *(float2*)&out[ob + (size_t)(rowl + 8) * 64 + col] = w1;
        }
        return;
    }

    // ---- write fp16 partials + fp32 l ----
    const size_t pq = (((size_t)(b * NQT2 + qt)) * NCH + chunk) * QT2;
    #pragma unroll
    for (int nt = 0; nt < 8; nt++) {
        const int col = nt * 8 + ((lane & 3) << 1);
        *(uint32_t*)&g_pacc[(pq + rowl) * 64 + col]     = packh(o[nt][0], o[nt][1]);
        *(uint32_t*)&g_pacc[(pq + rowl + 8) * 64 + col] = packh(o[nt][2], o[nt][3]);
    }
    if ((lane & 3) == 0) {
        g_pl[pq + rowl]     = lsum[0];
        g_pl[pq + rowl + 8] = lsum[2];
    }
}

// ---------------------------------------------------------------------------
// combine split-K partials for t >= 512 (qt2 >= 4). 4 h per thread.
// Unrolled predicated chunk loop -> 4-way MLP.
// grid = ((T-512)*16/256 = 96, B), block = 256.
// ---------------------------------------------------------------------------
__global__ void __launch_bounds__(256) combine_kernel(float* __restrict__ out)
{
    const int b   = blockIdx.y;
    const int gid = blockIdx.x * 256 + threadIdx.x;
    const int t   = 512 + (gid >> 4);
    const int hg  = (gid & 15) << 2;
    const int qt  = t >> 7;            // 128-row query tiles
    const int qi  = t & 127;
    const int nch = (t >> 9) + 1;

    const size_t base = ((size_t)(b * NQT2 + qt)) * NCH;
    float a0 = 0.f, a1 = 0.f, a2 = 0.f, a3 = 0.f;
    float L = 0.f;

    #pragma unroll
    for (int c = 0; c < NCH; c++) {
        if (c < nch) {
            const __half* p = &g_pacc[((base + c) * QT2 + qi) * 64 + hg];
            uint2 v = *(const uint2*)p;
            float2 f0 = __half22float2(*(__half2*)&v.x);
            float2 f1 = __half22float2(*(__half2*)&v.y);
            a0 += f0.x; a1 += f0.y; a2 += f1.x; a3 += f1.y;
            L += g_pl[(base + c) * QT2 + qi];
        }
    }

    const float inv = 1.f / L;
    float4 w;
    w.x = a0 * inv; w.y = a1 * inv; w.z = a2 * inv; w.w = a3 * inv;
    *(float4*)&out[((size_t)(b * T + t)) * 64 + hg] = w;
}

extern "C" void kernel_launch(void* const* d_in, const int* in_sizes, int n_in,
                              void* d_out, int out_size)
{
    const float* x  = (const float*)d_in[0];
    const float* Wk = (const float*)d_in[1];
    const float* Wq = (const float*)d_in[2];
    const float* Wv = (const float*)d_in[3];

    cudaFuncSetAttribute(proj_gemm_kernel,
                         cudaFuncAttributeMaxDynamicSharedMemorySize, 3 * BUFSZ);
    cudaFuncSetAttribute(attn_kernel,
                         cudaFuncAttributeMaxDynamicSharedMemorySize, ATTN_SMEM);

    convw_kernel<<<192, 128>>>(Wk, Wq, Wv);
    proj_gemm_kernel<<<256, 256, 3 * BUFSZ>>>(x);
    attn_kernel<<<dim3(NCH, NQT2, B), 256, ATTN_SMEM>>>((float*)d_out);
    combine_kernel<<<dim3((T - 512) * 16 / 256, B), 256>>>((float*)d_out);
}

// round 16
// speedup vs baseline: 1.0972x; 1.0972x over previous
#include <cuda_runtime.h>
#include <cuda_fp16.h>
#include <cstdint>

#define B 8
#define T 2048
#define C 1024
#define H 64
#define QTILE 64
#define NQT   (T / QTILE)
#define KCHUNK 512
#define NCH    4

// ---------------- scratch (__device__ globals; no allocation allowed) -------
__device__ __half g_pacc[B * NQT * NCH * QTILE * H];   // fp16 split-K partials
__device__ float  g_pl[B * NQT * NCH * QTILE];
__device__ __half g_wt[3 * H * C];          // W^T fp16: [192 n][1024 k]
// projected q/k/v as fp16 (q pre-scaled by log2(e)/32)
__device__ __half g_qh[B * T * H];
__device__ __half g_kh[B * T * H];
__device__ __half g_vh[B * T * H];

#define ONES_H2 0x3C003C00u

// ---------------- helpers ----------------------------------------------------
__device__ __forceinline__ uint32_t smem_u32(const void* p) {
    uint32_t a;
    asm("{ .reg .u64 t; cvta.to.shared.u64 t, %1; cvt.u32.u64 %0, t; }"
        : "=r"(a) : "l"(p));
    return a;
}
__device__ __forceinline__ void cp16(uint32_t saddr, const void* gptr) {
    asm volatile("cp.async.cg.shared.global [%0], [%1], 16;"
                 :: "r"(saddr), "l"(__cvta_generic_to_global(gptr)) : "memory");
}
#define CP_COMMIT() asm volatile("cp.async.commit_group;" ::: "memory")
#define CP_WAIT(n)  asm volatile("cp.async.wait_group %0;" :: "n"(n) : "memory")

__device__ __forceinline__ void ldx4(uint32_t* r, uint32_t addr) {
    asm volatile("ldmatrix.sync.aligned.m8n8.x4.shared.b16 {%0,%1,%2,%3}, [%4];"
                 : "=r"(r[0]), "=r"(r[1]), "=r"(r[2]), "=r"(r[3]) : "r"(addr));
}
__device__ __forceinline__ void ldx4t(uint32_t* r, uint32_t addr) {
    asm volatile("ldmatrix.sync.aligned.m8n8.x4.trans.shared.b16 {%0,%1,%2,%3}, [%4];"
                 : "=r"(r[0]), "=r"(r[1]), "=r"(r[2]), "=r"(r[3]) : "r"(addr));
}
__device__ __forceinline__ void mma_f16(float* c, const uint32_t* a,
                                        uint32_t b0, uint32_t b1) {
    asm volatile(
        "mma.sync.aligned.m16n8k16.row.col.f32.f16.f16.f32 "
        "{%0,%1,%2,%3}, {%4,%5,%6,%7}, {%8,%9}, {%0,%1,%2,%3};"
        : "+f"(c[0]), "+f"(c[1]), "+f"(c[2]), "+f"(c[3])
        : "r"(a[0]), "r"(a[1]), "r"(a[2]), "r"(a[3]), "r"(b0), "r"(b1));
}
__device__ __forceinline__ uint32_t packh(float lo, float hi) {
    uint32_t r;
    asm("cvt.rn.f16x2.f32 %0, %1, %2;" : "=r"(r) : "f"(hi), "f"(lo));
    return r;
}
__device__ __forceinline__ uint32_t h2ex2(uint32_t x) {
    uint32_t r;
    asm("ex2.approx.f16x2 %0, %1;" : "=r"(r) : "r"(x));
    return r;
}
__device__ __forceinline__ void sts8(uint32_t addr, uint32_t a, uint32_t b) {
    asm volatile("st.shared.v2.b32 [%0], {%1,%2};" :: "r"(addr), "r"(a), "r"(b) : "memory");
}

// ---------------------------------------------------------------------------
// W -> transposed fp16 via smem transpose. grid = 192, block = 128.
// ---------------------------------------------------------------------------
__global__ void __launch_bounds__(128) convw_kernel(
    const float* __restrict__ Wk, const float* __restrict__ Wq,
    const float* __restrict__ Wv)
{
    __shared__ float s[16][65];
    const int bid = blockIdx.x;
    const int o   = bid >> 6;
    const int k0  = (bid & 63) << 4;
    const int tid = threadIdx.x;
    const float* __restrict__ W = (o == 0) ? Wk : ((o == 1) ? Wq : Wv);

    #pragma unroll
    for (int i = 0; i < 2; i++) {
        int f = tid + 128 * i;
        int row = f >> 4, q4 = (f & 15) << 2;
        float4 v = *(const float4*)&W[(size_t)(k0 + row) * 64 + q4];
        s[row][q4 + 0] = v.x;
        s[row][q4 + 1] = v.y;
        s[row][q4 + 2] = v.z;
        s[row][q4 + 3] = v.w;
    }
    __syncthreads();

    #pragma unroll
    for (int i = 0; i < 2; i++) {
        int f = tid + 128 * i;
        int n = f >> 2, k = (f & 3) << 2;
        uint2 w;
        w.x = packh(s[k + 0][n], s[k + 1][n]);
        w.y = packh(s[k + 2][n], s[k + 3][n]);
        *(uint2*)&g_wt[((size_t)(o * 64 + n)) * 1024 + k0 + k] = w;
    }
}

// ---------------------------------------------------------------------------
// Projection GEMM — pure fp16 HMMA. x converted in-kernel.
// Block tile 128x192 (512 threads, 4x4 warps, warp tile 32x48), k chunk 32.
// 3-stage smem ring, ONE sync per chunk. Halves W L2 re-read traffic vs the
// 64-row tile (each block amortizes B over 2x the M rows).
// smem per buffer (25600 B): A @0 (128*80), B @10240 (192*80); 3 buffers.
// ---------------------------------------------------------------------------
#define BUFSZ 25600
#define B_OFF 10240

__device__ __forceinline__ void ldg_a(const float* __restrict__ x, int m0,
                                      int ch, int tid, float4* r)
{
    const int k0 = ch << 5;
    #pragma unroll
    for (int i = 0; i < 2; i++) {
        int idx = tid + 512 * i;           // 0..1023 (128 rows x 8 float4)
        int row = idx >> 3, q = idx & 7;
        r[i] = *(const float4*)&x[(size_t)(m0 + row) * 1024 + k0 + q * 4];
    }
}
__device__ __forceinline__ void sts_a(uint32_t base, int tid, const float4* r)
{
    #pragma unroll
    for (int i = 0; i < 2; i++) {
        int idx = tid + 512 * i;
        int row = idx >> 3, q = idx & 7;
        sts8(base + row * 80 + q * 8,
             packh(r[i].x, r[i].y), packh(r[i].z, r[i].w));
    }
}
__device__ __forceinline__ void stage_b(uint32_t base, int ch, int tid)
{
    const int k0 = ch << 5;
    #pragma unroll
    for (int i = 0; i < 2; i++) {
        int idx = tid + 512 * i;           // need 0..767
        if (idx < 768) {
            int r = idx >> 2, q = idx & 3;
            cp16(base + B_OFF + r * 80 + q * 16,
                 g_wt + (size_t)r * 1024 + k0 + q * 8);
        }
    }
}

__global__ void __launch_bounds__(512, 1) proj_gemm_kernel(const float* __restrict__ x)
{
    extern __shared__ __align__(16) char sm[];
    const uint32_t smb = smem_u32(sm);

    const int tid  = threadIdx.x;
    const int wid  = tid >> 5;
    const int lane = tid & 31;
    const int wr   = wid >> 2;          // 0..3 (32 rows each => 128)
    const int wc   = wid & 3;           // 0..3 (48 cols each => 192)
    const int m0   = blockIdx.x * 128;

    float c[2][6][4];
    #pragma unroll
    for (int mt = 0; mt < 2; mt++)
        #pragma unroll
        for (int nt = 0; nt < 6; nt++)
            #pragma unroll
            for (int e = 0; e < 4; e++) c[mt][nt][e] = 0.f;

    const uint32_t aoff = (uint32_t)((wr * 32 + (lane & 15)) * 80 + (lane >> 4) * 16);
    const int bg = lane >> 3;
    const uint32_t boff = (uint32_t)((wc * 48 + (lane & 7) + (bg >> 1) * 8) * 80 + (bg & 1) * 16);

    float4 areg[2];
    ldg_a(x, m0, 0, tid, areg);
    sts_a(smb, tid, areg);
    stage_b(smb, 0, tid);
    CP_COMMIT();
    ldg_a(x, m0, 1, tid, areg);
    stage_b(smb + BUFSZ, 1, tid);
    CP_COMMIT();

    int bufc = 0;
    for (int ch = 0; ch < 32; ch++) {
        if (ch < 31) { CP_WAIT(1); } else { CP_WAIT(0); }
        __syncthreads();

        int b1 = bufc + 1; if (b1 >= 3) b1 -= 3;
        if (ch + 1 < 32)
            sts_a(smb + b1 * BUFSZ, tid, areg);

        const uint32_t base = smb + bufc * BUFSZ;
        #pragma unroll
        for (int k16 = 0; k16 < 2; k16++) {
            uint32_t ah[2][4], bw[3][4];
            #pragma unroll
            for (int mt = 0; mt < 2; mt++)
                ldx4(ah[mt], base + aoff + mt * (16 * 80) + k16 * 32);
            #pragma unroll
            for (int np = 0; np < 3; np++)
                ldx4(bw[np], base + B_OFF + boff + np * (16 * 80) + k16 * 32);
            #pragma unroll
            for (int mt = 0; mt < 2; mt++) {
                #pragma unroll
                for (int nt = 0; nt < 6; nt++) {
                    const int np = nt >> 1, sel = (nt & 1) * 2;
                    mma_f16(c[mt][nt], ah[mt], bw[np][sel], bw[np][sel + 1]);
                }
            }
        }

        if (ch + 2 < 32) {
            ldg_a(x, m0, ch + 2, tid, areg);
            int b2 = bufc + 2; if (b2 >= 3) b2 -= 3;
            stage_b(smb + b2 * BUFSZ, ch + 2, tid);
            CP_COMMIT();
        }
        if (++bufc == 3) bufc = 0;
    }

    // Epilogue: fp16 q/k/v (q scaled by log2(e)/32 so attn uses ex2 directly)
    #pragma unroll
    for (int mt = 0; mt < 2; mt++) {
        const int row = m0 + wr * 32 + mt * 16 + (lane >> 2);
        #pragma unroll
        for (int nt = 0; nt < 6; nt++) {
            const int ng  = wc * 48 + nt * 8;
            const int mat = ng >> 6;
            const int col = (ng & 63) + 2 * (lane & 3);
            __half* dh = (mat == 0) ? g_kh : ((mat == 1) ? g_qh : g_vh);
            const float s = (mat == 1) ? 0.04508422f : 1.0f;   // log2e/32
            *(uint32_t*)&dh[(size_t)row * 64 + col] =
                packh(c[mt][nt][0] * s, c[mt][nt][1] * s);
            *(uint32_t*)&dh[(size_t)(row + 8) * 64 + col] =
                packh(c[mt][nt][2] * s, c[mt][nt][3] * s);
        }
    }
}

// ---------------------------------------------------------------------------
// Tensor-core split-K causal attention — fp16 operands, fp32 accum.
// grid = (NCH=4, NQT, B), heavy qt first. KCHUNK=512 (up to 8 k-tiles).
// 3-stage KV ring, ONE sync per tile. Q overlays buf2's K region.
// __launch_bounds__(128,4): 4 CTAs/SM (smem 48KB).     [round-14 best shape]
// ---------------------------------------------------------------------------
#define KVBUF   16384
#define ATTN_SMEM 49152

__device__ __forceinline__ void stage_kv(uint32_t base, int b, int s0, int tid)
{
    const size_t g0 = ((size_t)(b * T) + s0) * 64;
    #pragma unroll
    for (int i = 0; i < 4; i++) {
        int idx = tid + 128 * i;
        int row = idx >> 3, q = idx & 7;
        uint32_t dst = base + row * 128 + ((q ^ (row & 7)) << 4);
        size_t src = g0 + row * 64 + q * 8;
        cp16(dst,        g_kh + src);
        cp16(dst + 8192, g_vh + src);
    }
}

__global__ void __launch_bounds__(128, 4) attn_kernel(float* __restrict__ out)
{
    const int chunk = blockIdx.x;
    const int qt    = NQT - 1 - (int)blockIdx.y;   // heavy tiles first
    const int b     = blockIdx.z;
    const int nch   = (qt >> 3) + 1;

    const int kbeg = chunk * KCHUNK;
    const int klim = (qt + 1) * QTILE;
    if (kbeg >= klim) return;
    const int ntiles = min(8, (klim - kbeg) >> 6);

    extern __shared__ __align__(16) char sm[];
    const uint32_t smb = smem_u32(sm);
    const int tid  = threadIdx.x;
    const int w    = tid >> 5;
    const int lane = tid & 31;

    // prologue: Q (buf2 K-region overlay) + KV0 in group0; KV1 in group1
    {
        const size_t gq = ((size_t)(b * T) + qt * 64) * 64;
        #pragma unroll
        for (int i = 0; i < 4; i++) {
            int idx = tid + 128 * i;
            int row = idx >> 3, q = idx & 7;
            uint32_t dst = smb + 2 * KVBUF + row * 128 + ((q ^ (row & 7)) << 4);
            cp16(dst, g_qh + gq + row * 64 + q * 8);
        }
    }
    stage_kv(smb, b, kbeg, tid);
    CP_COMMIT();
    if (ntiles > 1) {
        stage_kv(smb + KVBUF, b, kbeg + 64, tid);
        CP_COMMIT();
        CP_WAIT(1);
    } else {
        CP_WAIT(0);
    }
    __syncthreads();

    // Q fragments -> registers
    uint32_t qh[4][4];
    #pragma unroll
    for (int ks = 0; ks < 4; ks++) {
        int row = w * 16 + (lane & 15);
        int cg  = ks * 2 + (lane >> 4);
        ldx4(qh[ks], smb + 2 * KVBUF + row * 128 + ((cg ^ (row & 7)) << 4));
    }

    float o[8][4];
    #pragma unroll
    for (int nt = 0; nt < 8; nt++)
        #pragma unroll
        for (int e = 0; e < 4; e++) o[nt][e] = 0.f;
    float lsum[4] = {0.f, 0.f, 0.f, 0.f};

    int bufc = 0;
    for (int kt = 0; kt < ntiles; kt++) {
        if (kt + 1 < ntiles) { CP_WAIT(1); } else { CP_WAIT(0); }
        __syncthreads();

        const uint32_t base = smb + bufc * KVBUF;

        // ---- S' = Q . K^T (log2 domain) ----
        float c[8][4];
        #pragma unroll
        for (int nt = 0; nt < 8; nt++)
            #pragma unroll
            for (int e = 0; e < 4; e++) c[nt][e] = 0.f;

        #pragma unroll
        for (int nb = 0; nb < 4; nb++) {
            #pragma unroll
            for (int ks = 0; ks < 4; ks++) {
                int row = nb * 16 + (lane & 7) + ((lane >> 4) << 3);
                int cg  = ks * 2 + ((lane >> 3) & 1);
                uint32_t bh[4];
                ldx4(bh, base + row * 128 + ((cg ^ (row & 7)) << 4));
                mma_f16(c[2 * nb],     qh[ks], bh[0], bh[1]);
                mma_f16(c[2 * nb + 1], qh[ks], bh[2], bh[3]);
            }
        }

        // ---- pack, 2^s in f16x2, mask ----
        const bool diag = (kbeg + kt * 64) == qt * 64;
        const int trow = w * 16 + (lane >> 2);
        uint32_t ph[8][2];
        #pragma unroll
        for (int nt = 0; nt < 8; nt++) {
            uint32_t p01 = h2ex2(packh(c[nt][0], c[nt][1]));
            uint32_t p23 = h2ex2(packh(c[nt][2], c[nt][3]));
            if (diag) {
                const int s0l = nt * 8 + ((lane & 3) << 1);
                uint32_t m01 = (s0l + 1 <= trow) ? 0xFFFFFFFFu
                             : ((s0l <= trow) ? 0x0000FFFFu : 0u);
                uint32_t m23 = (s0l + 1 <= trow + 8) ? 0xFFFFFFFFu
                             : ((s0l <= trow + 8) ? 0x0000FFFFu : 0u);
                p01 &= m01;
                p23 &= m23;
            }
            ph[nt][0] = p01;
            ph[nt][1] = p23;
        }

        // ---- O += P . V ;  l += P . 1 (tensor-core row sums) ----
        #pragma unroll
        for (int ks = 0; ks < 4; ks++) {
            uint32_t pa[4];
            pa[0] = ph[2 * ks][0];
            pa[1] = ph[2 * ks][1];
            pa[2] = ph[2 * ks + 1][0];
            pa[3] = ph[2 * ks + 1][1];
            mma_f16(lsum, pa, ONES_H2, ONES_H2);
            #pragma unroll
            for (int hb = 0; hb < 4; hb++) {
                int vrow = ks * 16 + (lane & 15);
                int cg   = hb * 2 + (lane >> 4);
                uint32_t vh[4];
                ldx4t(vh, base + 8192 + vrow * 128 + ((cg ^ (vrow & 7)) << 4));
                mma_f16(o[2 * hb],     pa, vh[0], vh[1]);
                mma_f16(o[2 * hb + 1], pa, vh[2], vh[3]);
            }
        }

        // ---- stage tile kt+2 into buf((kt+2)%3) (readers done pre-sync) ----
        if (kt + 2 < ntiles) {
            int bs = bufc + 2; if (bs >= 3) bs -= 3;
            stage_kv(smb + bs * KVBUF, b, kbeg + (kt + 2) * 64, tid);
            CP_COMMIT();
        }
        if (++bufc == 3) bufc = 0;
    }

    const int row = w * 16 + (lane >> 2);

    // ---- single-chunk tiles (qt<8): normalize in registers, write out ----
    if (nch == 1) {
        const float i0 = 1.f / lsum[0];
        const float i2 = 1.f / lsum[2];
        const size_t ob = ((size_t)(b * T) + qt * 64) * 64;
        #pragma unroll
        for (int nt = 0; nt < 8; nt++) {
            const int col = nt * 8 + ((lane & 3) << 1);
            float2 w0; w0.x = o[nt][0] * i0; w0.y = o[nt][1] * i0;
            float2 w1; w1.x = o[nt][2] * i2; w1.y = o[nt][3] * i2;
            *(float2*)&out[ob + (size_t)row * 64 + col]       = w0;
            *(float2*)&out[ob + (size_t)(row + 8) * 64 + col] = w1;
        }
        return;
    }

    // ---- write fp16 partials + fp32 l ----
    const size_t pq = (((size_t)(b * NQT + qt)) * NCH + chunk) * 64;
    #pragma unroll
    for (int nt = 0; nt < 8; nt++) {
        const int col = nt * 8 + ((lane & 3) << 1);
        *(uint32_t*)&g_pacc[(pq + row) * 64 + col]     = packh(o[nt][0], o[nt][1]);
        *(uint32_t*)&g_pacc[(pq + row + 8) * 64 + col] = packh(o[nt][2], o[nt][3]);
    }
    if ((lane & 3) == 0) {
        g_pl[pq + row]     = lsum[0];
        g_pl[pq + row + 8] = lsum[2];
    }
}

// ---------------------------------------------------------------------------
// combine split-K partials for t >= 512 (qt >= 8). 4 h per thread.
// Unrolled predicated chunk loop -> 4-way MLP.
// grid = ((T-512)*16/256 = 96, B), block = 256.
// ---------------------------------------------------------------------------
__global__ void __launch_bounds__(256) combine_kernel(float* __restrict__ out)
{
    const int b   = blockIdx.y;
    const int gid = blockIdx.x * 256 + threadIdx.x;
    const int t   = 512 + (gid >> 4);
    const int hg  = (gid & 15) << 2;
    const int qt  = t >> 6;
    const int qi  = t & 63;
    const int nch = (t >> 9) + 1;

    const size_t base = ((size_t)(b * NQT + qt)) * NCH;
    float a0 = 0.f, a1 = 0.f, a2 = 0.f, a3 = 0.f;
    float L = 0.f;

    #pragma unroll
    for (int c = 0; c < NCH; c++) {
        if (c < nch) {
            const __half* p = &g_pacc[((base + c) * 64 + qi) * 64 + hg];
            uint2 v = *(const uint2*)p;
            float2 f0 = __half22float2(*(__half2*)&v.x);
            float2 f1 = __half22float2(*(__half2*)&v.y);
            a0 += f0.x; a1 += f0.y; a2 += f1.x; a3 += f1.y;
            L += g_pl[(base + c) * 64 + qi];
        }
    }

    const float inv = 1.f / L;
    float4 w;
    w.x = a0 * inv; w.y = a1 * inv; w.z = a2 * inv; w.w = a3 * inv;
    *(float4*)&out[((size_t)(b * T + t)) * 64 + hg] = w;
}

extern "C" void kernel_launch(void* const* d_in, const int* in_sizes, int n_in,
                              void* d_out, int out_size)
{
    const float* x  = (const float*)d_in[0];
    const float* Wk = (const float*)d_in[1];
    const float* Wq = (const float*)d_in[2];
    const float* Wv = (const float*)d_in[3];

    cudaFuncSetAttribute(proj_gemm_kernel,
                         cudaFuncAttributeMaxDynamicSharedMemorySize, 3 * BUFSZ);
    cudaFuncSetAttribute(attn_kernel,
                         cudaFuncAttributeMaxDynamicSharedMemorySize, ATTN_SMEM);

    convw_kernel<<<192, 128>>>(Wk, Wq, Wv);
    proj_gemm_kernel<<<128, 512, 3 * BUFSZ>>>(x);
    attn_kernel<<<dim3(NCH, NQT, B), 128, ATTN_SMEM>>>((float*)d_out);
    combine_kernel<<<dim3((T - 512) * 16 / 256, B), 256>>>((float*)d_out);
}